// round 1
// baseline (speedup 1.0000x reference)
#include <cuda_runtime.h>
#include <math.h>

// ---------------- problem constants (fixed shapes) ----------------
#define NN    20000     // nodes
#define TT    8         // seq len
#define DSX   16        // static dim
#define DDIM  8         // dynamic dim
#define EE    320000    // edges before self loops
#define HLX   128       // lstm hidden
#define GHX   4         // gat heads
#define GCX   128       // channels per head
#define HCX   512       // GH*GC
#define EMBX  64
#define IN1X  (DSX + HLX)       // 144
#define ETOT  (EE + NN)         // 340000 edges incl self loops

// ---------------- scratch (__device__ globals; no cudaMalloc allowed) ------
__device__ float g_hs[TT * NN * HLX];       // all lstm hidden states [T][N][HL]
__device__ float g_c[NN * HLX];             // lstm cell state
__device__ float g_bufA[NN * HCX];          // xl / lstm gates
__device__ float g_bufB[NN * HCX];          // xr
__device__ float g_bufC[NN * HCX];          // gat out
__device__ float g_bufD[NN * HCX];          // bn out
__device__ float g_bsum[4 * HLX];           // b_ih + b_hh
__device__ float g_sum[HCX];
__device__ float g_sumsq[HCX];
__device__ float g_scale[HCX];
__device__ float g_shift[HCX];
__device__ int   g_deg[NN];
__device__ int   g_off[NN + 1];
__device__ int   g_cursor[NN];
__device__ int   g_csr[ETOT];

// ---------------- CSR build ----------------
__global__ void bsum_kernel(const float* __restrict__ b_ih, const float* __restrict__ b_hh) {
    int i = threadIdx.x;
    if (i < 4 * HLX) g_bsum[i] = b_ih[i] + b_hh[i];
}

__global__ void init_deg_kernel() {
    int i = blockIdx.x * blockDim.x + threadIdx.x;
    if (i < NN) g_deg[i] = 1;   // self loop
}

__global__ void count_kernel(const int* __restrict__ ei) {
    int i = blockIdx.x * blockDim.x + threadIdx.x;
    if (i < EE) atomicAdd(&g_deg[ei[EE + i]], 1);
}

__global__ void scan_kernel() {
    __shared__ int s[1024];
    const int t = threadIdx.x;
    const int CH = (NN + 1023) / 1024;      // 20
    int beg = t * CH;
    int end = beg + CH; if (end > NN) end = NN;
    int sum = 0;
    for (int i = beg; i < end; i++) sum += g_deg[i];
    int v = sum;
    s[t] = v;
    __syncthreads();
    for (int off = 1; off < 1024; off <<= 1) {
        int add = (t >= off) ? s[t - off] : 0;
        __syncthreads();
        v += add;
        s[t] = v;
        __syncthreads();
    }
    int run = (t == 0) ? 0 : s[t - 1];
    for (int i = beg; i < end; i++) { g_off[i] = run; run += g_deg[i]; }
    if (t == 1023) g_off[NN] = s[1023];
}

__global__ void cursor_kernel() {
    int i = blockIdx.x * blockDim.x + threadIdx.x;
    if (i < NN) g_cursor[i] = g_off[i];
}

__global__ void fill_kernel(const int* __restrict__ ei) {
    int i = blockIdx.x * blockDim.x + threadIdx.x;
    if (i < EE) {
        int s = ei[i];
        int d = ei[EE + i];
        int pos = atomicAdd(&g_cursor[d], 1);
        g_csr[pos] = s;
    } else if (i < ETOT) {
        int d = i - EE;
        int pos = atomicAdd(&g_cursor[d], 1);
        g_csr[pos] = d;       // self loop
    }
}

// ---------------- generic SGEMM:  C[M,Ncols] = [A1|A2] @ [B1|B2]^T (+bias) ----
// A split on K: A(r,k) = k<K1 ? A1[r*lda1+k] : A2[r*lda2+k-K1]  (A2==null -> 0)
// B is [Ncols, K] logically:   B(c,k) = k<K1 ? B1[c*ldb1+k] : B2[c*ldb2+k-K1]
#define BM 64
#define BN 64
#define BK 16
#define TM 4
#define TN 4

__global__ __launch_bounds__(256)
void gemm_kernel(int M, int Ncols, int K1, int K2,
                 const float* __restrict__ A1, int lda1,
                 const float* __restrict__ A2, int lda2,
                 const float* __restrict__ B1, int ldb1,
                 const float* __restrict__ B2, int ldb2,
                 const float* __restrict__ bias,
                 float* __restrict__ C, int ldc)
{
    __shared__ float As[BM][BK + 1];
    __shared__ float Bs[BN][BK + 1];
    const int K = K1 + K2;
    const int brow = blockIdx.x * BM;
    const int bcol = blockIdx.y * BN;
    const int tid = threadIdx.x;
    const int tx = tid & 15;
    const int ty = tid >> 4;

    float acc[TM][TN];
#pragma unroll
    for (int i = 0; i < TM; i++)
#pragma unroll
        for (int j = 0; j < TN; j++) acc[i][j] = 0.f;

    for (int k0 = 0; k0 < K; k0 += BK) {
#pragma unroll
        for (int i = 0; i < 4; i++) {
            int idx = tid + i * 256;
            int r = idx / BK, kk = idx % BK;
            int gr = brow + r, gk = k0 + kk;
            float v = 0.f;
            if (gr < M && gk < K) {
                if (gk < K1)      v = A1[(size_t)gr * lda1 + gk];
                else if (A2)      v = A2[(size_t)gr * lda2 + (gk - K1)];
            }
            As[r][kk] = v;
        }
#pragma unroll
        for (int i = 0; i < 4; i++) {
            int idx = tid + i * 256;
            int c = idx / BK, kk = idx % BK;
            int gc = bcol + c, gk = k0 + kk;
            float v = 0.f;
            if (gc < Ncols && gk < K) {
                if (gk < K1)      v = B1[(size_t)gc * ldb1 + gk];
                else              v = B2[(size_t)gc * ldb2 + (gk - K1)];
            }
            Bs[c][kk] = v;
        }
        __syncthreads();
#pragma unroll
        for (int kk = 0; kk < BK; kk++) {
            float a[TM], b[TN];
#pragma unroll
            for (int i = 0; i < TM; i++) a[i] = As[ty * TM + i][kk];
#pragma unroll
            for (int j = 0; j < TN; j++) b[j] = Bs[tx * TN + j][kk];
#pragma unroll
            for (int i = 0; i < TM; i++)
#pragma unroll
                for (int j = 0; j < TN; j++) acc[i][j] += a[i] * b[j];
        }
        __syncthreads();
    }

#pragma unroll
    for (int i = 0; i < TM; i++) {
        int gr = brow + ty * TM + i;
        if (gr >= M) continue;
#pragma unroll
        for (int j = 0; j < TN; j++) {
            int gc = bcol + tx * TN + j;
            if (gc >= Ncols) continue;
            float v = acc[i][j];
            if (bias) v += bias[gc];
            C[(size_t)gr * ldc + gc] = v;
        }
    }
}

// ---------------- LSTM gate nonlinearity ----------------
__device__ __forceinline__ float sigm(float x) { return 1.f / (1.f + __expf(-x)); }

__global__ void lstm_gate_kernel(const float* __restrict__ G, int t) {
    int i = blockIdx.x * blockDim.x + threadIdx.x;
    if (i >= NN * HLX) return;
    int n = i / HLX, j = i % HLX;
    const float* g = G + (size_t)n * (4 * HLX);
    float gi = sigm(g[j]);
    float gf = sigm(g[HLX + j]);
    float gg = tanhf(g[2 * HLX + j]);
    float go = sigm(g[3 * HLX + j]);
    float cold = (t == 0) ? 0.f : g_c[i];
    float c = gf * cold + gi * gg;
    g_c[i] = c;
    g_hs[(size_t)t * NN * HLX + i] = go * tanhf(c);
}

// ---------------- GATv2 aggregation: one block per dst, one warp per head ----
// online softmax -> single gather of xl[src] per edge
__global__ void gat_kernel(const float* __restrict__ xl, const float* __restrict__ xr,
                           const float* __restrict__ att, const float* __restrict__ bias,
                           float* __restrict__ out)
{
    const int d = blockIdx.x;
    const int w = threadIdx.x >> 5;
    const int lane = threadIdx.x & 31;
    const int base = w * GCX + lane * 4;

    const float4 xrv = *reinterpret_cast<const float4*>(xr + (size_t)d * HCX + base);
    const float4 av  = *reinterpret_cast<const float4*>(att + w * GCX + lane * 4);

    float m = -1e30f, den = 0.f;
    float4 acc = make_float4(0.f, 0.f, 0.f, 0.f);

    const int beg = g_off[d], end = g_off[d + 1];
    for (int idx = beg; idx < end; idx++) {
        int s = g_csr[idx];
        float4 xlv = *reinterpret_cast<const float4*>(xl + (size_t)s * HCX + base);
        float ex = xlv.x + xrv.x; ex = ex > 0.f ? ex : 0.2f * ex;
        float ey = xlv.y + xrv.y; ey = ey > 0.f ? ey : 0.2f * ey;
        float ez = xlv.z + xrv.z; ez = ez > 0.f ? ez : 0.2f * ez;
        float ew = xlv.w + xrv.w; ew = ew > 0.f ? ew : 0.2f * ew;
        float p = ex * av.x + ey * av.y + ez * av.z + ew * av.w;
#pragma unroll
        for (int off = 16; off; off >>= 1) p += __shfl_xor_sync(0xffffffffu, p, off);
        float nm = fmaxf(m, p);
        float sc = __expf(m - nm);          // exp(-inf)=0 on first edge
        float e  = __expf(p - nm);
        acc.x = acc.x * sc + e * xlv.x;
        acc.y = acc.y * sc + e * xlv.y;
        acc.z = acc.z * sc + e * xlv.z;
        acc.w = acc.w * sc + e * xlv.w;
        den = den * sc + e;
        m = nm;
    }
    float inv = 1.f / den;                  // den>0: self loop guaranteed
    float4 bv = *reinterpret_cast<const float4*>(bias + base);
    float4 o;
    o.x = acc.x * inv + bv.x;
    o.y = acc.y * inv + bv.y;
    o.z = acc.z * inv + bv.z;
    o.w = acc.w * inv + bv.w;
    *reinterpret_cast<float4*>(out + (size_t)d * HCX + base) = o;
}

// ---------------- BatchNorm ----------------
__global__ void zero_stats_kernel() {
    int c = threadIdx.x;
    if (c < HCX) { g_sum[c] = 0.f; g_sumsq[c] = 0.f; }
}

#define BN_ROWS 200
__global__ void bn_stats_kernel(const float* __restrict__ x) {
    int c = threadIdx.x;              // 256 threads -> channels c and c+256
    int rb = blockIdx.x * BN_ROWS;
    int re = rb + BN_ROWS; if (re > NN) re = NN;
    float s0 = 0.f, s1 = 0.f, q0 = 0.f, q1 = 0.f;
    for (int r = rb; r < re; r++) {
        float v0 = x[(size_t)r * HCX + c];
        float v1 = x[(size_t)r * HCX + c + 256];
        s0 += v0; q0 += v0 * v0;
        s1 += v1; q1 += v1 * v1;
    }
    atomicAdd(&g_sum[c], s0);
    atomicAdd(&g_sum[c + 256], s1);
    atomicAdd(&g_sumsq[c], q0);
    atomicAdd(&g_sumsq[c + 256], q1);
}

__global__ void bn_finalize_kernel(const float* __restrict__ gamma, const float* __restrict__ beta) {
    int c = threadIdx.x;
    if (c >= HCX) return;
    float mean = g_sum[c] * (1.f / NN);
    float var  = g_sumsq[c] * (1.f / NN) - mean * mean;
    float a = gamma[c] * rsqrtf(var + 1e-5f);
    g_scale[c] = a;
    g_shift[c] = beta[c] - mean * a;
}

__global__ void bn_apply_kernel(const float* __restrict__ x, float* __restrict__ y) {
    int i = blockIdx.x * blockDim.x + threadIdx.x;   // float4 index
    if (i >= NN * HCX / 4) return;
    int c4 = (i & 127) * 4;                          // 512/4=128 float4 per row
    float4 v = reinterpret_cast<const float4*>(x)[i];
    float4 o;
    o.x = fmaxf(0.f, v.x * g_scale[c4 + 0] + g_shift[c4 + 0]);
    o.y = fmaxf(0.f, v.y * g_scale[c4 + 1] + g_shift[c4 + 1]);
    o.z = fmaxf(0.f, v.z * g_scale[c4 + 2] + g_shift[c4 + 2]);
    o.w = fmaxf(0.f, v.w * g_scale[c4 + 3] + g_shift[c4 + 3]);
    reinterpret_cast<float4*>(y)[i] = o;
}

// ---------------- host side ----------------
static inline void launch_gemm(int M, int Ncols, int K1, int K2,
                               const float* A1, int lda1, const float* A2, int lda2,
                               const float* B1, int ldb1, const float* B2, int ldb2,
                               const float* bias, float* C, int ldc)
{
    dim3 grid((M + BM - 1) / BM, (Ncols + BN - 1) / BN);
    gemm_kernel<<<grid, 256>>>(M, Ncols, K1, K2, A1, lda1, A2, lda2,
                               B1, ldb1, B2, ldb2, bias, C, ldc);
}

extern "C" void kernel_launch(void* const* d_in, const int* in_sizes, int n_in,
                              void* d_out, int out_size)
{
    const float* x_static = (const float*)d_in[0];
    const float* dyn      = (const float*)d_in[1];
    const int*   ei       = (const int*)  d_in[2];
    const float* W_ih     = (const float*)d_in[3];
    const float* W_hh     = (const float*)d_in[4];
    const float* b_ih     = (const float*)d_in[5];
    const float* b_hh     = (const float*)d_in[6];
    const float* Wl1      = (const float*)d_in[7];
    const float* Wr1      = (const float*)d_in[8];
    const float* att1     = (const float*)d_in[9];
    const float* bg1      = (const float*)d_in[10];
    const float* Wl2      = (const float*)d_in[11];
    const float* Wr2      = (const float*)d_in[12];
    const float* att2     = (const float*)d_in[13];
    const float* bg2      = (const float*)d_in[14];
    const float* gamma1   = (const float*)d_in[15];
    const float* beta1    = (const float*)d_in[16];
    const float* gamma2   = (const float*)d_in[17];
    const float* beta2    = (const float*)d_in[18];
    const float* Wp       = (const float*)d_in[19];
    const float* bp       = (const float*)d_in[20];
    float* out = (float*)d_out;

    void* p;
    cudaGetSymbolAddress(&p, g_hs);   float* hs  = (float*)p;
    cudaGetSymbolAddress(&p, g_bufA); float* bA  = (float*)p;
    cudaGetSymbolAddress(&p, g_bufB); float* bB  = (float*)p;
    cudaGetSymbolAddress(&p, g_bufC); float* bC  = (float*)p;
    cudaGetSymbolAddress(&p, g_bufD); float* bD  = (float*)p;
    cudaGetSymbolAddress(&p, g_bsum); float* bsum = (float*)p;

    // --- setup: fused bias + CSR build (dst-sorted, amortized over 16 GAT calls)
    bsum_kernel<<<1, 512>>>(b_ih, b_hh);
    init_deg_kernel<<<(NN + 255) / 256, 256>>>();
    count_kernel<<<(EE + 255) / 256, 256>>>(ei);
    scan_kernel<<<1, 1024>>>();
    cursor_kernel<<<(NN + 255) / 256, 256>>>();
    fill_kernel<<<(ETOT + 255) / 256, 256>>>(ei);

    // --- LSTM over T steps
    for (int t = 0; t < TT; t++) {
        const float* hprev = (t == 0) ? nullptr : (hs + (size_t)(t - 1) * NN * HLX);
        launch_gemm(NN, 4 * HLX, DDIM, HLX,
                    dyn + t * DDIM, TT * DDIM, hprev, HLX,
                    W_ih, DDIM, W_hh, HLX,
                    bsum, bA, 4 * HLX);
        lstm_gate_kernel<<<(NN * HLX + 255) / 256, 256>>>(bA, t);
    }

    // --- per-timestep GNN
    for (int t = 0; t < TT; t++) {
        const float* ht = hs + (size_t)t * NN * HLX;

        // layer 1: xl/xr = [x_static | h_t] @ W^T
        launch_gemm(NN, HCX, DSX, HLX, x_static, DSX, ht, HLX,
                    Wl1, IN1X, Wl1 + DSX, IN1X, nullptr, bA, HCX);
        launch_gemm(NN, HCX, DSX, HLX, x_static, DSX, ht, HLX,
                    Wr1, IN1X, Wr1 + DSX, IN1X, nullptr, bB, HCX);
        gat_kernel<<<NN, 128>>>(bA, bB, att1, bg1, bC);

        zero_stats_kernel<<<1, 512>>>();
        bn_stats_kernel<<<(NN + BN_ROWS - 1) / BN_ROWS, 256>>>(bC);
        bn_finalize_kernel<<<1, 512>>>(gamma1, beta1);
        bn_apply_kernel<<<(NN * HCX / 4 + 255) / 256, 256>>>(bC, bD);

        // layer 2
        launch_gemm(NN, HCX, HCX, 0, bD, HCX, nullptr, 0,
                    Wl2, HCX, nullptr, 0, nullptr, bA, HCX);
        launch_gemm(NN, HCX, HCX, 0, bD, HCX, nullptr, 0,
                    Wr2, HCX, nullptr, 0, nullptr, bB, HCX);
        gat_kernel<<<NN, 128>>>(bA, bB, att2, bg2, bC);

        zero_stats_kernel<<<1, 512>>>();
        bn_stats_kernel<<<(NN + BN_ROWS - 1) / BN_ROWS, 256>>>(bC);
        bn_finalize_kernel<<<1, 512>>>(gamma2, beta2);
        bn_apply_kernel<<<(NN * HCX / 4 + 255) / 256, 256>>>(bC, bD);

        // projection into output slice [:, t, :]
        launch_gemm(NN, EMBX, HCX, 0, bD, HCX, nullptr, 0,
                    Wp, HCX, nullptr, 0, bp, out + t * EMBX, TT * EMBX);
    }
}

// round 2
// speedup vs baseline: 3.3649x; 3.3649x over previous
#include <cuda_runtime.h>
#include <math.h>
#include <stdint.h>

// ---------------- problem constants (fixed shapes) ----------------
#define NN    20000     // nodes
#define TT    8         // seq len
#define DSX   16        // static dim
#define DDIM  8         // dynamic dim
#define EE    320000    // edges before self loops
#define HLX   128       // lstm hidden
#define GHX   4         // gat heads
#define GCX   128       // channels per head
#define HCX   512       // GH*GC
#define EMBX  64
#define IN1X  (DSX + HLX)       // 144
#define ETOT  (EE + NN)         // 340000 edges incl self loops

// ---------------- scratch (__device__ globals; no cudaMalloc allowed) ------
__device__ float g_hs[TT * NN * HLX];       // all lstm hidden states [T][N][HL]
__device__ float g_c[NN * HLX];             // lstm cell state
__device__ float g_bufA[NN * HCX];          // xl / lstm gates
__device__ float g_bufB[NN * HCX];          // xr
__device__ float g_bufC[NN * HCX];          // gat out
__device__ float g_bufD[NN * HCX];          // bn out
__device__ float g_bsum[4 * HLX];           // b_ih + b_hh
__device__ float g_sum[HCX];
__device__ float g_sumsq[HCX];
__device__ float g_scale[HCX];
__device__ float g_shift[HCX];
__device__ int   g_deg[NN];
__device__ int   g_off[NN + 1];
__device__ int   g_cursor[NN];
__device__ int   g_csr[ETOT];

// ---------------- CSR build ----------------
__global__ void bsum_kernel(const float* __restrict__ b_ih, const float* __restrict__ b_hh) {
    int i = threadIdx.x;
    if (i < 4 * HLX) g_bsum[i] = b_ih[i] + b_hh[i];
}

__global__ void init_deg_kernel() {
    int i = blockIdx.x * blockDim.x + threadIdx.x;
    if (i < NN) g_deg[i] = 1;   // self loop
}

__global__ void count_kernel(const int* __restrict__ ei) {
    int i = blockIdx.x * blockDim.x + threadIdx.x;
    if (i < EE) atomicAdd(&g_deg[ei[EE + i]], 1);
}

__global__ void scan_kernel() {
    __shared__ int s[1024];
    const int t = threadIdx.x;
    const int CH = (NN + 1023) / 1024;      // 20
    int beg = t * CH;
    int end = beg + CH; if (end > NN) end = NN;
    int sum = 0;
    for (int i = beg; i < end; i++) sum += g_deg[i];
    int v = sum;
    s[t] = v;
    __syncthreads();
    for (int off = 1; off < 1024; off <<= 1) {
        int add = (t >= off) ? s[t - off] : 0;
        __syncthreads();
        v += add;
        s[t] = v;
        __syncthreads();
    }
    int run = (t == 0) ? 0 : s[t - 1];
    for (int i = beg; i < end; i++) { g_off[i] = run; run += g_deg[i]; }
    if (t == 1023) g_off[NN] = s[1023];
}

__global__ void cursor_kernel() {
    int i = blockIdx.x * blockDim.x + threadIdx.x;
    if (i < NN) g_cursor[i] = g_off[i];
}

__global__ void fill_kernel(const int* __restrict__ ei) {
    int i = blockIdx.x * blockDim.x + threadIdx.x;
    if (i < EE) {
        int s = ei[i];
        int d = ei[EE + i];
        int pos = atomicAdd(&g_cursor[d], 1);
        g_csr[pos] = s;
    } else if (i < ETOT) {
        int d = i - EE;
        int pos = atomicAdd(&g_cursor[d], 1);
        g_csr[pos] = d;       // self loop
    }
}

// ---------------- tf32 tensor-core GEMM ----------------
// C[M,Ncols] = [A1|A2] @ [B1|B2]^T (+bias)
//   A(r,k) = k<K1 ? A1[r*lda1+k] : A2[r*lda2+k-K1]   (A2==null -> 0)
//   B(c,k) = k<K1 ? B1[c*ldb1+k] : B2[c*ldb2+k-K1]
// Constraints used: K % 4 == 0, K1 % 4 == 0, all pointers 16B aligned,
// ldc even (for float2 stores).  Verified for every call site.
#define GBM 128
#define GBN 128
#define GBK 16
#define SKP 20   // smem row pitch (floats) -> conflict-free quad access

__device__ __forceinline__ uint32_t f2tf(float f) {
    uint32_t u;
    asm("cvt.rna.tf32.f32 %0, %1;" : "=r"(u) : "f"(f));
    return u;
}

__device__ __forceinline__ float4 fetch_split(const float* __restrict__ P1, int ld1,
                                              const float* __restrict__ P2, int ld2,
                                              int K1, int K, int r, int gk, int R)
{
    float4 z = make_float4(0.f, 0.f, 0.f, 0.f);
    if (r >= R || gk >= K) return z;
    if (gk < K1) return *reinterpret_cast<const float4*>(P1 + (size_t)r * ld1 + gk);
    if (P2)      return *reinterpret_cast<const float4*>(P2 + (size_t)r * ld2 + (gk - K1));
    return z;
}

__device__ __forceinline__ void mma_tf32(float c[4], uint32_t a0, uint32_t a1,
                                         uint32_t a2, uint32_t a3,
                                         uint32_t b0, uint32_t b1)
{
    asm volatile(
        "mma.sync.aligned.m16n8k8.row.col.f32.tf32.tf32.f32 "
        "{%0,%1,%2,%3}, {%4,%5,%6,%7}, {%8,%9}, {%0,%1,%2,%3};\n"
        : "+f"(c[0]), "+f"(c[1]), "+f"(c[2]), "+f"(c[3])
        : "r"(a0), "r"(a1), "r"(a2), "r"(a3), "r"(b0), "r"(b1));
}

__global__ __launch_bounds__(256)
void gemm_tc_kernel(int M, int Ncols, int K1, int K2,
                    const float* __restrict__ A1, int lda1,
                    const float* __restrict__ A2, int lda2,
                    const float* __restrict__ B1, int ldb1,
                    const float* __restrict__ B2, int ldb2,
                    const float* __restrict__ bias,
                    float* __restrict__ C, int ldc)
{
    __shared__ uint32_t As[GBM][SKP];
    __shared__ uint32_t Bs[GBN][SKP];

    const int K = K1 + K2;
    const int ktiles = (K + GBK - 1) / GBK;
    const int tid = threadIdx.x;
    const int brow = blockIdx.x * GBM;
    const int bcol = blockIdx.y * GBN;
    const int lane = tid & 31;
    const int warp = tid >> 5;
    const int g    = lane >> 2;     // group id 0..7
    const int tig  = lane & 3;      // thread-in-group
    const int wm   = warp & 1;      // warp row (2)
    const int wn   = warp >> 1;     // warp col (4)

    const int arow = tid >> 2;        // 0..63
    const int kq   = (tid & 3) * 4;   // 0,4,8,12

    float acc[4][4][4];
#pragma unroll
    for (int mt = 0; mt < 4; mt++)
#pragma unroll
        for (int nt = 0; nt < 4; nt++)
#pragma unroll
            for (int i = 0; i < 4; i++) acc[mt][nt][i] = 0.f;

    // prologue: tile 0
    float4 rA0 = fetch_split(A1, lda1, A2, lda2, K1, K, brow + arow,      kq, M);
    float4 rA1 = fetch_split(A1, lda1, A2, lda2, K1, K, brow + arow + 64, kq, M);
    float4 rB0 = fetch_split(B1, ldb1, B2, ldb2, K1, K, bcol + arow,      kq, Ncols);
    float4 rB1 = fetch_split(B1, ldb1, B2, ldb2, K1, K, bcol + arow + 64, kq, Ncols);

    for (int kt = 0; kt < ktiles; kt++) {
        // store staged tile to smem (tf32 convert)
        As[arow     ][kq+0] = f2tf(rA0.x); As[arow     ][kq+1] = f2tf(rA0.y);
        As[arow     ][kq+2] = f2tf(rA0.z); As[arow     ][kq+3] = f2tf(rA0.w);
        As[arow + 64][kq+0] = f2tf(rA1.x); As[arow + 64][kq+1] = f2tf(rA1.y);
        As[arow + 64][kq+2] = f2tf(rA1.z); As[arow + 64][kq+3] = f2tf(rA1.w);
        Bs[arow     ][kq+0] = f2tf(rB0.x); Bs[arow     ][kq+1] = f2tf(rB0.y);
        Bs[arow     ][kq+2] = f2tf(rB0.z); Bs[arow     ][kq+3] = f2tf(rB0.w);
        Bs[arow + 64][kq+0] = f2tf(rB1.x); Bs[arow + 64][kq+1] = f2tf(rB1.y);
        Bs[arow + 64][kq+2] = f2tf(rB1.z); Bs[arow + 64][kq+3] = f2tf(rB1.w);
        __syncthreads();

        // stage next tile
        if (kt + 1 < ktiles) {
            int k0 = (kt + 1) * GBK;
            rA0 = fetch_split(A1, lda1, A2, lda2, K1, K, brow + arow,      k0 + kq, M);
            rA1 = fetch_split(A1, lda1, A2, lda2, K1, K, brow + arow + 64, k0 + kq, M);
            rB0 = fetch_split(B1, ldb1, B2, ldb2, K1, K, bcol + arow,      k0 + kq, Ncols);
            rB1 = fetch_split(B1, ldb1, B2, ldb2, K1, K, bcol + arow + 64, k0 + kq, Ncols);
        }

        // compute: two k8 steps
#pragma unroll
        for (int ks = 0; ks < 2; ks++) {
            const int kb = ks * 8;
            uint32_t af[4][4], bf[4][2];
#pragma unroll
            for (int mt = 0; mt < 4; mt++) {
                int r0 = wm * 64 + mt * 16 + g;
                af[mt][0] = As[r0    ][kb + tig];
                af[mt][1] = As[r0 + 8][kb + tig];
                af[mt][2] = As[r0    ][kb + tig + 4];
                af[mt][3] = As[r0 + 8][kb + tig + 4];
            }
#pragma unroll
            for (int nt = 0; nt < 4; nt++) {
                int cb = wn * 32 + nt * 8 + g;
                bf[nt][0] = Bs[cb][kb + tig];
                bf[nt][1] = Bs[cb][kb + tig + 4];
            }
#pragma unroll
            for (int mt = 0; mt < 4; mt++)
#pragma unroll
                for (int nt = 0; nt < 4; nt++)
                    mma_tf32(acc[mt][nt], af[mt][0], af[mt][1], af[mt][2], af[mt][3],
                             bf[nt][0], bf[nt][1]);
        }
        __syncthreads();
    }

    // epilogue
#pragma unroll
    for (int mt = 0; mt < 4; mt++) {
        int gr0 = brow + wm * 64 + mt * 16 + g;
        int gr1 = gr0 + 8;
#pragma unroll
        for (int nt = 0; nt < 4; nt++) {
            int gc = bcol + wn * 32 + nt * 8 + 2 * tig;
            if (gc >= Ncols) continue;
            float bx = bias ? bias[gc]     : 0.f;
            float by = bias ? bias[gc + 1] : 0.f;
            if (gr0 < M) {
                float2 v = make_float2(acc[mt][nt][0] + bx, acc[mt][nt][1] + by);
                *reinterpret_cast<float2*>(C + (size_t)gr0 * ldc + gc) = v;
            }
            if (gr1 < M) {
                float2 v = make_float2(acc[mt][nt][2] + bx, acc[mt][nt][3] + by);
                *reinterpret_cast<float2*>(C + (size_t)gr1 * ldc + gc) = v;
            }
        }
    }
}

// ---------------- LSTM gate nonlinearity ----------------
__device__ __forceinline__ float sigm(float x) { return 1.f / (1.f + __expf(-x)); }

__global__ void lstm_gate_kernel(const float* __restrict__ G, int t) {
    int i = blockIdx.x * blockDim.x + threadIdx.x;
    if (i >= NN * HLX) return;
    int n = i / HLX, j = i % HLX;
    const float* g = G + (size_t)n * (4 * HLX);
    float gi = sigm(g[j]);
    float gf = sigm(g[HLX + j]);
    float gg = tanhf(g[2 * HLX + j]);
    float go = sigm(g[3 * HLX + j]);
    float cold = (t == 0) ? 0.f : g_c[i];
    float c = gf * cold + gi * gg;
    g_c[i] = c;
    g_hs[(size_t)t * NN * HLX + i] = go * tanhf(c);
}

// ---------------- GATv2 aggregation: one block per dst, one warp per head ----
__global__ void gat_kernel(const float* __restrict__ xl, const float* __restrict__ xr,
                           const float* __restrict__ att, const float* __restrict__ bias,
                           float* __restrict__ out)
{
    const int d = blockIdx.x;
    const int w = threadIdx.x >> 5;
    const int lane = threadIdx.x & 31;
    const int base = w * GCX + lane * 4;

    const float4 xrv = *reinterpret_cast<const float4*>(xr + (size_t)d * HCX + base);
    const float4 av  = *reinterpret_cast<const float4*>(att + w * GCX + lane * 4);

    float m = -1e30f, den = 0.f;
    float4 acc = make_float4(0.f, 0.f, 0.f, 0.f);

    const int beg = g_off[d], end = g_off[d + 1];
    for (int idx = beg; idx < end; idx++) {
        int s = g_csr[idx];
        float4 xlv = *reinterpret_cast<const float4*>(xl + (size_t)s * HCX + base);
        float ex = xlv.x + xrv.x; ex = ex > 0.f ? ex : 0.2f * ex;
        float ey = xlv.y + xrv.y; ey = ey > 0.f ? ey : 0.2f * ey;
        float ez = xlv.z + xrv.z; ez = ez > 0.f ? ez : 0.2f * ez;
        float ew = xlv.w + xrv.w; ew = ew > 0.f ? ew : 0.2f * ew;
        float p = ex * av.x + ey * av.y + ez * av.z + ew * av.w;
#pragma unroll
        for (int off = 16; off; off >>= 1) p += __shfl_xor_sync(0xffffffffu, p, off);
        float nm = fmaxf(m, p);
        float sc = __expf(m - nm);
        float e  = __expf(p - nm);
        acc.x = acc.x * sc + e * xlv.x;
        acc.y = acc.y * sc + e * xlv.y;
        acc.z = acc.z * sc + e * xlv.z;
        acc.w = acc.w * sc + e * xlv.w;
        den = den * sc + e;
        m = nm;
    }
    float inv = 1.f / den;
    float4 bv = *reinterpret_cast<const float4*>(bias + base);
    float4 o;
    o.x = acc.x * inv + bv.x;
    o.y = acc.y * inv + bv.y;
    o.z = acc.z * inv + bv.z;
    o.w = acc.w * inv + bv.w;
    *reinterpret_cast<float4*>(out + (size_t)d * HCX + base) = o;
}

// ---------------- BatchNorm ----------------
__global__ void zero_stats_kernel() {
    int c = threadIdx.x;
    if (c < HCX) { g_sum[c] = 0.f; g_sumsq[c] = 0.f; }
}

#define BN_ROWS 200
__global__ void bn_stats_kernel(const float* __restrict__ x) {
    int c = threadIdx.x;
    int rb = blockIdx.x * BN_ROWS;
    int re = rb + BN_ROWS; if (re > NN) re = NN;
    float s0 = 0.f, s1 = 0.f, q0 = 0.f, q1 = 0.f;
    for (int r = rb; r < re; r++) {
        float v0 = x[(size_t)r * HCX + c];
        float v1 = x[(size_t)r * HCX + c + 256];
        s0 += v0; q0 += v0 * v0;
        s1 += v1; q1 += v1 * v1;
    }
    atomicAdd(&g_sum[c], s0);
    atomicAdd(&g_sum[c + 256], s1);
    atomicAdd(&g_sumsq[c], q0);
    atomicAdd(&g_sumsq[c + 256], q1);
}

__global__ void bn_finalize_kernel(const float* __restrict__ gamma, const float* __restrict__ beta) {
    int c = threadIdx.x;
    if (c >= HCX) return;
    float mean = g_sum[c] * (1.f / NN);
    float var  = g_sumsq[c] * (1.f / NN) - mean * mean;
    float a = gamma[c] * rsqrtf(var + 1e-5f);
    g_scale[c] = a;
    g_shift[c] = beta[c] - mean * a;
}

__global__ void bn_apply_kernel(const float* __restrict__ x, float* __restrict__ y) {
    int i = blockIdx.x * blockDim.x + threadIdx.x;
    if (i >= NN * HCX / 4) return;
    int c4 = (i & 127) * 4;
    float4 v = reinterpret_cast<const float4*>(x)[i];
    float4 o;
    o.x = fmaxf(0.f, v.x * g_scale[c4 + 0] + g_shift[c4 + 0]);
    o.y = fmaxf(0.f, v.y * g_scale[c4 + 1] + g_shift[c4 + 1]);
    o.z = fmaxf(0.f, v.z * g_scale[c4 + 2] + g_shift[c4 + 2]);
    o.w = fmaxf(0.f, v.w * g_scale[c4 + 3] + g_shift[c4 + 3]);
    reinterpret_cast<float4*>(y)[i] = o;
}

// ---------------- host side ----------------
static inline void launch_gemm(int M, int Ncols, int K1, int K2,
                               const float* A1, int lda1, const float* A2, int lda2,
                               const float* B1, int ldb1, const float* B2, int ldb2,
                               const float* bias, float* C, int ldc)
{
    dim3 grid((M + GBM - 1) / GBM, (Ncols + GBN - 1) / GBN);
    gemm_tc_kernel<<<grid, 256>>>(M, Ncols, K1, K2, A1, lda1, A2, lda2,
                                  B1, ldb1, B2, ldb2, bias, C, ldc);
}

extern "C" void kernel_launch(void* const* d_in, const int* in_sizes, int n_in,
                              void* d_out, int out_size)
{
    const float* x_static = (const float*)d_in[0];
    const float* dyn      = (const float*)d_in[1];
    const int*   ei       = (const int*)  d_in[2];
    const float* W_ih     = (const float*)d_in[3];
    const float* W_hh     = (const float*)d_in[4];
    const float* b_ih     = (const float*)d_in[5];
    const float* b_hh     = (const float*)d_in[6];
    const float* Wl1      = (const float*)d_in[7];
    const float* Wr1      = (const float*)d_in[8];
    const float* att1     = (const float*)d_in[9];
    const float* bg1      = (const float*)d_in[10];
    const float* Wl2      = (const float*)d_in[11];
    const float* Wr2      = (const float*)d_in[12];
    const float* att2     = (const float*)d_in[13];
    const float* bg2      = (const float*)d_in[14];
    const float* gamma1   = (const float*)d_in[15];
    const float* beta1    = (const float*)d_in[16];
    const float* gamma2   = (const float*)d_in[17];
    const float* beta2    = (const float*)d_in[18];
    const float* Wp       = (const float*)d_in[19];
    const float* bp       = (const float*)d_in[20];
    float* out = (float*)d_out;

    void* p;
    cudaGetSymbolAddress(&p, g_hs);   float* hs  = (float*)p;
    cudaGetSymbolAddress(&p, g_bufA); float* bA  = (float*)p;
    cudaGetSymbolAddress(&p, g_bufB); float* bB  = (float*)p;
    cudaGetSymbolAddress(&p, g_bufC); float* bC  = (float*)p;
    cudaGetSymbolAddress(&p, g_bufD); float* bD  = (float*)p;
    cudaGetSymbolAddress(&p, g_bsum); float* bsum = (float*)p;

    // --- setup: fused bias + CSR build (amortized over all 16 GAT calls)
    bsum_kernel<<<1, 512>>>(b_ih, b_hh);
    init_deg_kernel<<<(NN + 255) / 256, 256>>>();
    count_kernel<<<(EE + 255) / 256, 256>>>(ei);
    scan_kernel<<<1, 1024>>>();
    cursor_kernel<<<(NN + 255) / 256, 256>>>();
    fill_kernel<<<(ETOT + 255) / 256, 256>>>(ei);

    // --- LSTM over T steps
    for (int t = 0; t < TT; t++) {
        const float* hprev = (t == 0) ? nullptr : (hs + (size_t)(t - 1) * NN * HLX);
        launch_gemm(NN, 4 * HLX, DDIM, HLX,
                    dyn + t * DDIM, TT * DDIM, hprev, HLX,
                    W_ih, DDIM, W_hh, HLX,
                    bsum, bA, 4 * HLX);
        lstm_gate_kernel<<<(NN * HLX + 255) / 256, 256>>>(bA, t);
    }

    // --- per-timestep GNN
    for (int t = 0; t < TT; t++) {
        const float* ht = hs + (size_t)t * NN * HLX;

        // layer 1: xl/xr = [x_static | h_t] @ W^T
        launch_gemm(NN, HCX, DSX, HLX, x_static, DSX, ht, HLX,
                    Wl1, IN1X, Wl1 + DSX, IN1X, nullptr, bA, HCX);
        launch_gemm(NN, HCX, DSX, HLX, x_static, DSX, ht, HLX,
                    Wr1, IN1X, Wr1 + DSX, IN1X, nullptr, bB, HCX);
        gat_kernel<<<NN, 128>>>(bA, bB, att1, bg1, bC);

        zero_stats_kernel<<<1, 512>>>();
        bn_stats_kernel<<<(NN + BN_ROWS - 1) / BN_ROWS, 256>>>(bC);
        bn_finalize_kernel<<<1, 512>>>(gamma1, beta1);
        bn_apply_kernel<<<(NN * HCX / 4 + 255) / 256, 256>>>(bC, bD);

        // layer 2
        launch_gemm(NN, HCX, HCX, 0, bD, HCX, nullptr, 0,
                    Wl2, HCX, nullptr, 0, nullptr, bA, HCX);
        launch_gemm(NN, HCX, HCX, 0, bD, HCX, nullptr, 0,
                    Wr2, HCX, nullptr, 0, nullptr, bB, HCX);
        gat_kernel<<<NN, 128>>>(bA, bB, att2, bg2, bC);

        zero_stats_kernel<<<1, 512>>>();
        bn_stats_kernel<<<(NN + BN_ROWS - 1) / BN_ROWS, 256>>>(bC);
        bn_finalize_kernel<<<1, 512>>>(gamma2, beta2);
        bn_apply_kernel<<<(NN * HCX / 4 + 255) / 256, 256>>>(bC, bD);

        // projection into output slice [:, t, :]
        launch_gemm(NN, EMBX, HCX, 0, bD, HCX, nullptr, 0,
                    Wp, HCX, nullptr, 0, bp, out + t * EMBX, TT * EMBX);
    }
}

// round 3
// speedup vs baseline: 4.0062x; 1.1906x over previous
#include <cuda_runtime.h>
#include <math.h>
#include <stdint.h>

// ---------------- problem constants (fixed shapes) ----------------
#define NN    20000     // nodes
#define TT    8         // seq len
#define DSX   16        // static dim
#define DDIM  8         // dynamic dim
#define EE    320000    // edges before self loops
#define HLX   128       // lstm hidden
#define GHX   4         // gat heads
#define GCX   128       // channels per head
#define HCX   512       // GH*GC
#define EMBX  64
#define IN1X  (DSX + HLX)       // 144
#define ETOT  (EE + NN)         // 340000 edges incl self loops
#define TNN   (TT * NN)         // 160000 batched rows

// ---------------- scratch (__device__ globals; no cudaMalloc allowed) ------
__device__ float g_hs[TT * NN * HLX];       // all lstm hidden states [T][N][HL]
__device__ float g_c[NN * HLX];             // lstm cell state
__device__ float g_bufA[TT * NN * HCX];     // batched xl (also lstm gates)
__device__ float g_bufB[TT * NN * HCX];     // batched xr
__device__ float g_bufC[TT * NN * HCX];     // batched gat out
__device__ float g_xsl[NN * HCX];           // x_static @ Wl1_s^T
__device__ float g_xsr[NN * HCX];           // x_static @ Wr1_s^T
__device__ float g_bsum[4 * HLX];           // b_ih + b_hh
__device__ float g_sum[TT * HCX];
__device__ float g_sumsq[TT * HCX];
__device__ float g_scale[TT * HCX];
__device__ float g_shift[TT * HCX];
__device__ int   g_deg[NN];
__device__ int   g_off[NN + 1];
__device__ int   g_cursor[NN];
__device__ int   g_csr[ETOT];

// ---------------- CSR build ----------------
__global__ void bsum_kernel(const float* __restrict__ b_ih, const float* __restrict__ b_hh) {
    int i = threadIdx.x;
    if (i < 4 * HLX) g_bsum[i] = b_ih[i] + b_hh[i];
}

__global__ void init_deg_kernel() {
    int i = blockIdx.x * blockDim.x + threadIdx.x;
    if (i < NN) g_deg[i] = 1;   // self loop
}

__global__ void count_kernel(const int* __restrict__ ei) {
    int i = blockIdx.x * blockDim.x + threadIdx.x;
    if (i < EE) atomicAdd(&g_deg[ei[EE + i]], 1);
}

__global__ void scan_kernel() {
    __shared__ int s[1024];
    const int t = threadIdx.x;
    const int CH = (NN + 1023) / 1024;
    int beg = t * CH;
    int end = beg + CH; if (end > NN) end = NN;
    int sum = 0;
    for (int i = beg; i < end; i++) sum += g_deg[i];
    int v = sum;
    s[t] = v;
    __syncthreads();
    for (int off = 1; off < 1024; off <<= 1) {
        int add = (t >= off) ? s[t - off] : 0;
        __syncthreads();
        v += add;
        s[t] = v;
        __syncthreads();
    }
    int run = (t == 0) ? 0 : s[t - 1];
    for (int i = beg; i < end; i++) { g_off[i] = run; run += g_deg[i]; }
    if (t == 1023) g_off[NN] = s[1023];
}

__global__ void cursor_kernel() {
    int i = blockIdx.x * blockDim.x + threadIdx.x;
    if (i < NN) g_cursor[i] = g_off[i];
}

__global__ void fill_kernel(const int* __restrict__ ei) {
    int i = blockIdx.x * blockDim.x + threadIdx.x;
    if (i < EE) {
        int s = ei[i];
        int d = ei[EE + i];
        int pos = atomicAdd(&g_cursor[d], 1);
        g_csr[pos] = s;
    } else if (i < ETOT) {
        int d = i - EE;
        int pos = atomicAdd(&g_cursor[d], 1);
        g_csr[pos] = d;       // self loop
    }
}

// ---------------- tf32 tensor-core GEMM (batched, fused BN, remapped out) ----
// C[M,Ncols] = f([A1|A2]) @ [B1|B2]^T (+bias) (+addmat[r%NN])
//   A(r,k) = k<K1 ? A1[r*lda1+k] : A2[r*lda2+k-K1]   (A2==null -> 0)
//   B(c,k) = k<K1 ? B1[c*ldb1+k] : B2[c*ldb2+k-K1]
//   if asc: A element (r,k) -> relu(a*asc[(r/NN)*HCX+k] + ash[...]) (needs K==HCX)
//   if addmat: C[r][c] += addmat[(r%NN)*addld + c]
//   if oproj: C store offset = (r%NN)*(TT*EMBX) + (r/NN)*EMBX + c
// Constraints: K%4==0, K1%4==0, 16B-aligned pointers, even column starts.
#define GBM 128
#define GBN 128
#define GBK 16
#define SKP 20   // smem row pitch -> conflict-free quad access

__device__ __forceinline__ uint32_t f2tf(float f) {
    uint32_t u;
    asm("cvt.rna.tf32.f32 %0, %1;" : "=r"(u) : "f"(f));
    return u;
}

__device__ __forceinline__ float4 fetch_split(const float* __restrict__ P1, int ld1,
                                              const float* __restrict__ P2, int ld2,
                                              int K1, int K, int r, int gk, int R,
                                              const float* __restrict__ asc,
                                              const float* __restrict__ ash)
{
    float4 z = make_float4(0.f, 0.f, 0.f, 0.f);
    if (r >= R || gk >= K) return z;
    float4 v;
    if (gk < K1)      v = *reinterpret_cast<const float4*>(P1 + (size_t)r * ld1 + gk);
    else if (P2)      v = *reinterpret_cast<const float4*>(P2 + (size_t)r * ld2 + (gk - K1));
    else              return z;
    if (asc) {
        int t = r / NN;
        const float* sc = asc + (size_t)t * HCX + gk;
        const float* sh = ash + (size_t)t * HCX + gk;
        v.x = fmaxf(0.f, v.x * sc[0] + sh[0]);
        v.y = fmaxf(0.f, v.y * sc[1] + sh[1]);
        v.z = fmaxf(0.f, v.z * sc[2] + sh[2]);
        v.w = fmaxf(0.f, v.w * sc[3] + sh[3]);
    }
    return v;
}

__device__ __forceinline__ void mma_tf32(float c[4], uint32_t a0, uint32_t a1,
                                         uint32_t a2, uint32_t a3,
                                         uint32_t b0, uint32_t b1)
{
    asm volatile(
        "mma.sync.aligned.m16n8k8.row.col.f32.tf32.tf32.f32 "
        "{%0,%1,%2,%3}, {%4,%5,%6,%7}, {%8,%9}, {%0,%1,%2,%3};\n"
        : "+f"(c[0]), "+f"(c[1]), "+f"(c[2]), "+f"(c[3])
        : "r"(a0), "r"(a1), "r"(a2), "r"(a3), "r"(b0), "r"(b1));
}

__global__ __launch_bounds__(256)
void gemm_tc_kernel(int M, int Ncols, int K1, int K2,
                    const float* __restrict__ A1, int lda1,
                    const float* __restrict__ A2, int lda2,
                    const float* __restrict__ B1, int ldb1,
                    const float* __restrict__ B2, int ldb2,
                    const float* __restrict__ bias,
                    const float* __restrict__ asc,
                    const float* __restrict__ ash,
                    const float* __restrict__ addmat, int addld,
                    float* __restrict__ C, int ldc, int oproj)
{
    __shared__ uint32_t As[2][GBM][SKP];
    __shared__ uint32_t Bs[2][GBN][SKP];

    const int K = K1 + K2;
    const int ktiles = (K + GBK - 1) / GBK;
    const int tid = threadIdx.x;
    const int brow = blockIdx.x * GBM;
    const int bcol = blockIdx.y * GBN;
    const int lane = tid & 31;
    const int warp = tid >> 5;
    const int g    = lane >> 2;
    const int tig  = lane & 3;
    const int wm   = warp & 1;
    const int wn   = warp >> 1;

    const int arow = tid >> 2;
    const int kq   = (tid & 3) * 4;

    float acc[4][4][4];
#pragma unroll
    for (int mt = 0; mt < 4; mt++)
#pragma unroll
        for (int nt = 0; nt < 4; nt++)
#pragma unroll
            for (int i = 0; i < 4; i++) acc[mt][nt][i] = 0.f;

    float4 rA0 = fetch_split(A1, lda1, A2, lda2, K1, K, brow + arow,      kq, M, asc, ash);
    float4 rA1 = fetch_split(A1, lda1, A2, lda2, K1, K, brow + arow + 64, kq, M, asc, ash);
    float4 rB0 = fetch_split(B1, ldb1, B2, ldb2, K1, K, bcol + arow,      kq, Ncols, 0, 0);
    float4 rB1 = fetch_split(B1, ldb1, B2, ldb2, K1, K, bcol + arow + 64, kq, Ncols, 0, 0);

    for (int kt = 0; kt < ktiles; kt++) {
        const int buf = kt & 1;
        As[buf][arow     ][kq+0] = f2tf(rA0.x); As[buf][arow     ][kq+1] = f2tf(rA0.y);
        As[buf][arow     ][kq+2] = f2tf(rA0.z); As[buf][arow     ][kq+3] = f2tf(rA0.w);
        As[buf][arow + 64][kq+0] = f2tf(rA1.x); As[buf][arow + 64][kq+1] = f2tf(rA1.y);
        As[buf][arow + 64][kq+2] = f2tf(rA1.z); As[buf][arow + 64][kq+3] = f2tf(rA1.w);
        Bs[buf][arow     ][kq+0] = f2tf(rB0.x); Bs[buf][arow     ][kq+1] = f2tf(rB0.y);
        Bs[buf][arow     ][kq+2] = f2tf(rB0.z); Bs[buf][arow     ][kq+3] = f2tf(rB0.w);
        Bs[buf][arow + 64][kq+0] = f2tf(rB1.x); Bs[buf][arow + 64][kq+1] = f2tf(rB1.y);
        Bs[buf][arow + 64][kq+2] = f2tf(rB1.z); Bs[buf][arow + 64][kq+3] = f2tf(rB1.w);
        __syncthreads();

        if (kt + 1 < ktiles) {
            int k0 = (kt + 1) * GBK;
            rA0 = fetch_split(A1, lda1, A2, lda2, K1, K, brow + arow,      k0 + kq, M, asc, ash);
            rA1 = fetch_split(A1, lda1, A2, lda2, K1, K, brow + arow + 64, k0 + kq, M, asc, ash);
            rB0 = fetch_split(B1, ldb1, B2, ldb2, K1, K, bcol + arow,      k0 + kq, Ncols, 0, 0);
            rB1 = fetch_split(B1, ldb1, B2, ldb2, K1, K, bcol + arow + 64, k0 + kq, Ncols, 0, 0);
        }

#pragma unroll
        for (int ks = 0; ks < 2; ks++) {
            const int kb = ks * 8;
            uint32_t af[4][4], bf[4][2];
#pragma unroll
            for (int mt = 0; mt < 4; mt++) {
                int r0 = wm * 64 + mt * 16 + g;
                af[mt][0] = As[buf][r0    ][kb + tig];
                af[mt][1] = As[buf][r0 + 8][kb + tig];
                af[mt][2] = As[buf][r0    ][kb + tig + 4];
                af[mt][3] = As[buf][r0 + 8][kb + tig + 4];
            }
#pragma unroll
            for (int nt = 0; nt < 4; nt++) {
                int cb = wn * 32 + nt * 8 + g;
                bf[nt][0] = Bs[buf][cb][kb + tig];
                bf[nt][1] = Bs[buf][cb][kb + tig + 4];
            }
#pragma unroll
            for (int mt = 0; mt < 4; mt++)
#pragma unroll
                for (int nt = 0; nt < 4; nt++)
                    mma_tf32(acc[mt][nt], af[mt][0], af[mt][1], af[mt][2], af[mt][3],
                             bf[nt][0], bf[nt][1]);
        }
        __syncthreads();
    }

    // epilogue
#pragma unroll
    for (int mt = 0; mt < 4; mt++) {
        int gr0 = brow + wm * 64 + mt * 16 + g;
        int gr1 = gr0 + 8;
#pragma unroll
        for (int nt = 0; nt < 4; nt++) {
            int gc = bcol + wn * 32 + nt * 8 + 2 * tig;
            if (gc >= Ncols) continue;
            float bx = bias ? bias[gc]     : 0.f;
            float by = bias ? bias[gc + 1] : 0.f;
            if (gr0 < M) {
                float ax = bx, ay = by;
                if (addmat) {
                    const float* ad = addmat + (size_t)(gr0 % NN) * addld + gc;
                    ax += ad[0]; ay += ad[1];
                }
                float2 v = make_float2(acc[mt][nt][0] + ax, acc[mt][nt][1] + ay);
                size_t off = oproj ? ((size_t)(gr0 % NN) * (TT * EMBX) + (gr0 / NN) * EMBX + gc)
                                   : ((size_t)gr0 * ldc + gc);
                *reinterpret_cast<float2*>(C + off) = v;
            }
            if (gr1 < M) {
                float ax = bx, ay = by;
                if (addmat) {
                    const float* ad = addmat + (size_t)(gr1 % NN) * addld + gc;
                    ax += ad[0]; ay += ad[1];
                }
                float2 v = make_float2(acc[mt][nt][2] + ax, acc[mt][nt][3] + ay);
                size_t off = oproj ? ((size_t)(gr1 % NN) * (TT * EMBX) + (gr1 / NN) * EMBX + gc)
                                   : ((size_t)gr1 * ldc + gc);
                *reinterpret_cast<float2*>(C + off) = v;
            }
        }
    }
}

// ---------------- LSTM gate nonlinearity ----------------
__device__ __forceinline__ float sigm(float x) { return 1.f / (1.f + __expf(-x)); }

__global__ void lstm_gate_kernel(const float* __restrict__ G, int t) {
    int i = blockIdx.x * blockDim.x + threadIdx.x;
    if (i >= NN * HLX) return;
    int n = i / HLX, j = i % HLX;
    const float* g = G + (size_t)n * (4 * HLX);
    float gi = sigm(g[j]);
    float gf = sigm(g[HLX + j]);
    float gg = tanhf(g[2 * HLX + j]);
    float go = sigm(g[3 * HLX + j]);
    float cold = (t == 0) ? 0.f : g_c[i];
    float c = gf * cold + gi * gg;
    g_c[i] = c;
    g_hs[(size_t)t * NN * HLX + i] = go * tanhf(c);
}

// ---------------- GATv2 aggregation (batched over t) ----------------
// grid (NN, TT); one warp per head; online softmax, single gather per edge
__global__ void gat_kernel(const float* __restrict__ xl, const float* __restrict__ xr,
                           const float* __restrict__ att, const float* __restrict__ bias,
                           float* __restrict__ out)
{
    const int d = blockIdx.x;
    const int t = blockIdx.y;
    const int w = threadIdx.x >> 5;
    const int lane = threadIdx.x & 31;
    const int base = w * GCX + lane * 4;
    const size_t tbase = (size_t)t * NN;

    const float4 xrv = *reinterpret_cast<const float4*>(xr + (tbase + d) * HCX + base);
    const float4 av  = *reinterpret_cast<const float4*>(att + w * GCX + lane * 4);

    float m = -1e30f, den = 0.f;
    float4 acc = make_float4(0.f, 0.f, 0.f, 0.f);

    const int beg = g_off[d], end = g_off[d + 1];
    for (int idx = beg; idx < end; idx++) {
        int s = g_csr[idx];
        float4 xlv = *reinterpret_cast<const float4*>(xl + (tbase + s) * HCX + base);
        float ex = xlv.x + xrv.x; ex = ex > 0.f ? ex : 0.2f * ex;
        float ey = xlv.y + xrv.y; ey = ey > 0.f ? ey : 0.2f * ey;
        float ez = xlv.z + xrv.z; ez = ez > 0.f ? ez : 0.2f * ez;
        float ew = xlv.w + xrv.w; ew = ew > 0.f ? ew : 0.2f * ew;
        float p = ex * av.x + ey * av.y + ez * av.z + ew * av.w;
#pragma unroll
        for (int off = 16; off; off >>= 1) p += __shfl_xor_sync(0xffffffffu, p, off);
        float nm = fmaxf(m, p);
        float sc = __expf(m - nm);
        float e  = __expf(p - nm);
        acc.x = acc.x * sc + e * xlv.x;
        acc.y = acc.y * sc + e * xlv.y;
        acc.z = acc.z * sc + e * xlv.z;
        acc.w = acc.w * sc + e * xlv.w;
        den = den * sc + e;
        m = nm;
    }
    float inv = 1.f / den;
    float4 bv = *reinterpret_cast<const float4*>(bias + base);
    float4 o;
    o.x = acc.x * inv + bv.x;
    o.y = acc.y * inv + bv.y;
    o.z = acc.z * inv + bv.z;
    o.w = acc.w * inv + bv.w;
    *reinterpret_cast<float4*>(out + (tbase + d) * HCX + base) = o;
}

// ---------------- BatchNorm (batched over t) ----------------
__global__ void zero_stats_kernel() {
    int c = blockIdx.x * blockDim.x + threadIdx.x;
    if (c < TT * HCX) { g_sum[c] = 0.f; g_sumsq[c] = 0.f; }
}

#define BN_ROWS 200
__global__ void bn_stats_kernel(const float* __restrict__ x) {
    int c = threadIdx.x;
    int t = blockIdx.y;
    const float* xt = x + (size_t)t * NN * HCX;
    int rb = blockIdx.x * BN_ROWS;
    int re = rb + BN_ROWS; if (re > NN) re = NN;
    float s0 = 0.f, s1 = 0.f, q0 = 0.f, q1 = 0.f;
    for (int r = rb; r < re; r++) {
        float v0 = xt[(size_t)r * HCX + c];
        float v1 = xt[(size_t)r * HCX + c + 256];
        s0 += v0; q0 += v0 * v0;
        s1 += v1; q1 += v1 * v1;
    }
    atomicAdd(&g_sum[t * HCX + c], s0);
    atomicAdd(&g_sum[t * HCX + c + 256], s1);
    atomicAdd(&g_sumsq[t * HCX + c], q0);
    atomicAdd(&g_sumsq[t * HCX + c + 256], q1);
}

__global__ void bn_finalize_kernel(const float* __restrict__ gamma, const float* __restrict__ beta) {
    int c = threadIdx.x;           // channel 0..511
    int t = blockIdx.x;
    int i = t * HCX + c;
    float mean = g_sum[i] * (1.f / NN);
    float var  = g_sumsq[i] * (1.f / NN) - mean * mean;
    float a = gamma[c] * rsqrtf(var + 1e-5f);
    g_scale[i] = a;
    g_shift[i] = beta[c] - mean * a;
}

// ---------------- host side ----------------
static inline void launch_gemm(int M, int Ncols, int K1, int K2,
                               const float* A1, int lda1, const float* A2, int lda2,
                               const float* B1, int ldb1, const float* B2, int ldb2,
                               const float* bias, const float* asc, const float* ash,
                               const float* addmat, int addld,
                               float* C, int ldc, int oproj)
{
    dim3 grid((M + GBM - 1) / GBM, (Ncols + GBN - 1) / GBN);
    gemm_tc_kernel<<<grid, 256>>>(M, Ncols, K1, K2, A1, lda1, A2, lda2,
                                  B1, ldb1, B2, ldb2, bias, asc, ash,
                                  addmat, addld, C, ldc, oproj);
}

extern "C" void kernel_launch(void* const* d_in, const int* in_sizes, int n_in,
                              void* d_out, int out_size)
{
    const float* x_static = (const float*)d_in[0];
    const float* dyn      = (const float*)d_in[1];
    const int*   ei       = (const int*)  d_in[2];
    const float* W_ih     = (const float*)d_in[3];
    const float* W_hh     = (const float*)d_in[4];
    const float* b_ih     = (const float*)d_in[5];
    const float* b_hh     = (const float*)d_in[6];
    const float* Wl1      = (const float*)d_in[7];
    const float* Wr1      = (const float*)d_in[8];
    const float* att1     = (const float*)d_in[9];
    const float* bg1      = (const float*)d_in[10];
    const float* Wl2      = (const float*)d_in[11];
    const float* Wr2      = (const float*)d_in[12];
    const float* att2     = (const float*)d_in[13];
    const float* bg2      = (const float*)d_in[14];
    const float* gamma1   = (const float*)d_in[15];
    const float* beta1    = (const float*)d_in[16];
    const float* gamma2   = (const float*)d_in[17];
    const float* beta2    = (const float*)d_in[18];
    const float* Wp       = (const float*)d_in[19];
    const float* bp       = (const float*)d_in[20];
    float* out = (float*)d_out;

    void* p;
    cudaGetSymbolAddress(&p, g_hs);    float* hs   = (float*)p;
    cudaGetSymbolAddress(&p, g_bufA);  float* bA   = (float*)p;
    cudaGetSymbolAddress(&p, g_bufB);  float* bB   = (float*)p;
    cudaGetSymbolAddress(&p, g_bufC);  float* bC   = (float*)p;
    cudaGetSymbolAddress(&p, g_xsl);   float* xsl  = (float*)p;
    cudaGetSymbolAddress(&p, g_xsr);   float* xsr  = (float*)p;
    cudaGetSymbolAddress(&p, g_bsum);  float* bsum = (float*)p;
    cudaGetSymbolAddress(&p, g_scale); float* bsc  = (float*)p;
    cudaGetSymbolAddress(&p, g_shift); float* bsh  = (float*)p;

    // --- setup: fused bias + CSR build
    bsum_kernel<<<1, 512>>>(b_ih, b_hh);
    init_deg_kernel<<<(NN + 255) / 256, 256>>>();
    count_kernel<<<(EE + 255) / 256, 256>>>(ei);
    scan_kernel<<<1, 1024>>>();
    cursor_kernel<<<(NN + 255) / 256, 256>>>();
    fill_kernel<<<(ETOT + 255) / 256, 256>>>(ei);

    // --- static projections for layer-1 (constant across t)
    launch_gemm(NN, HCX, DSX, 0, x_static, DSX, 0, 0,
                Wl1, IN1X, 0, 0, 0, 0, 0, 0, 0, xsl, HCX, 0);
    launch_gemm(NN, HCX, DSX, 0, x_static, DSX, 0, 0,
                Wr1, IN1X, 0, 0, 0, 0, 0, 0, 0, xsr, HCX, 0);

    // --- LSTM over T steps (sequential)
    for (int t = 0; t < TT; t++) {
        const float* hprev = (t == 0) ? nullptr : (hs + (size_t)(t - 1) * NN * HLX);
        launch_gemm(NN, 4 * HLX, DDIM, HLX,
                    dyn + t * DDIM, TT * DDIM, hprev, HLX,
                    W_ih, DDIM, W_hh, HLX,
                    bsum, 0, 0, 0, 0, bA, 4 * HLX, 0);
        lstm_gate_kernel<<<(NN * HLX + 255) / 256, 256>>>(bA, t);
    }

    // --- layer 1 (batched over all t): xl/xr = hs @ Wd^T + xs[r%NN]
    launch_gemm(TNN, HCX, HLX, 0, hs, HLX, 0, 0,
                Wl1 + DSX, IN1X, 0, 0, 0, 0, 0, xsl, HCX, bA, HCX, 0);
    launch_gemm(TNN, HCX, HLX, 0, hs, HLX, 0, 0,
                Wr1 + DSX, IN1X, 0, 0, 0, 0, 0, xsr, HCX, bB, HCX, 0);
    gat_kernel<<<dim3(NN, TT), 128>>>(bA, bB, att1, bg1, bC);

    zero_stats_kernel<<<TT, 512>>>();
    bn_stats_kernel<<<dim3((NN + BN_ROWS - 1) / BN_ROWS, TT), 256>>>(bC);
    bn_finalize_kernel<<<TT, 512>>>(gamma1, beta1);

    // --- layer 2 (batched, BN1+relu fused into A fetch)
    launch_gemm(TNN, HCX, HCX, 0, bC, HCX, 0, 0,
                Wl2, HCX, 0, 0, 0, bsc, bsh, 0, 0, bA, HCX, 0);
    launch_gemm(TNN, HCX, HCX, 0, bC, HCX, 0, 0,
                Wr2, HCX, 0, 0, 0, bsc, bsh, 0, 0, bB, HCX, 0);
    gat_kernel<<<dim3(NN, TT), 128>>>(bA, bB, att2, bg2, bC);

    zero_stats_kernel<<<TT, 512>>>();
    bn_stats_kernel<<<dim3((NN + BN_ROWS - 1) / BN_ROWS, TT), 256>>>(bC);
    bn_finalize_kernel<<<TT, 512>>>(gamma2, beta2);

    // --- projection (batched, BN2+relu fused, output remapped to [N,T,EMB])
    launch_gemm(TNN, EMBX, HCX, 0, bC, HCX, 0, 0,
                Wp, HCX, 0, 0, bp, bsc, bsh, 0, 0, out, 0, 1);
}

// round 4
// speedup vs baseline: 4.0424x; 1.0091x over previous
#include <cuda_runtime.h>
#include <math.h>
#include <stdint.h>

// ---------------- problem constants (fixed shapes) ----------------
#define NN    20000
#define TT    8
#define DSX   16
#define DDIM  8
#define EE    320000
#define HLX   128
#define GHX   4
#define GCX   128
#define HCX   512
#define EMBX  64
#define IN1X  (DSX + HLX)       // 144
#define ETOT  (EE + NN)
#define TNN   (TT * NN)         // 160000
#define XLD   (2 * HCX)         // 1024 combined xl|xr row stride

// ---------------- scratch ----------------
__device__ float g_hs[TT * NN * HLX];        // lstm hidden states [T][N][HL]
__device__ float g_c[NN * HLX];              // lstm cell state
__device__ float g_gate[NN * 4 * HLX];       // per-step recurrent gates
__device__ float g_gatesx[TNN * 4 * HLX];    // batched input-side gates [n*T+t][512]
__device__ float g_AB[(size_t)TNN * XLD];    // combined xl|xr [T*N][1024]
__device__ float g_bufC[TNN * HCX];          // gat out
__device__ float g_xscat[NN * XLD];          // x_static @ [Wl1s|Wr1s]^T
__device__ float g_WcatS[XLD * DSX];         // packed static weights layer1
__device__ float g_WcatD[XLD * HLX];         // packed dynamic weights layer1
__device__ float g_Wcat2[XLD * HCX];         // packed layer2 weights
__device__ float g_bsum[4 * HLX];
__device__ float g_sum[TT * HCX];
__device__ float g_sumsq[TT * HCX];
__device__ float g_scale[TT * HCX];
__device__ float g_shift[TT * HCX];
__device__ int   g_deg[NN];
__device__ int   g_off[NN + 1];
__device__ int   g_cursor[NN];
__device__ int   g_csr[ETOT];

// ---------------- setup kernels ----------------
__global__ void bsum_kernel(const float* __restrict__ b_ih, const float* __restrict__ b_hh) {
    int i = threadIdx.x;
    if (i < 4 * HLX) g_bsum[i] = b_ih[i] + b_hh[i];
}

__global__ void pack1_kernel(const float* __restrict__ Wl1, const float* __restrict__ Wr1) {
    int i = blockIdx.x * blockDim.x + threadIdx.x;
    if (i >= XLD * IN1X) return;
    int j = i / IN1X, k = i % IN1X;
    const float* W = (j < HCX) ? Wl1 : Wr1;
    int jj = j & (HCX - 1);
    float v = W[(size_t)jj * IN1X + k];
    if (k < DSX) g_WcatS[j * DSX + k] = v;
    else         g_WcatD[j * HLX + (k - DSX)] = v;
}

__global__ void pack2_kernel(const float* __restrict__ Wl2, const float* __restrict__ Wr2) {
    int i = blockIdx.x * blockDim.x + threadIdx.x;
    if (i >= XLD * HCX) return;
    int j = i / HCX, k = i % HCX;
    g_Wcat2[i] = (j < HCX) ? Wl2[(size_t)j * HCX + k] : Wr2[(size_t)(j - HCX) * HCX + k];
}

__global__ void init_deg_kernel() {
    int i = blockIdx.x * blockDim.x + threadIdx.x;
    if (i < NN) g_deg[i] = 1;
}

__global__ void count_kernel(const int* __restrict__ ei) {
    int i = blockIdx.x * blockDim.x + threadIdx.x;
    if (i < EE) atomicAdd(&g_deg[ei[EE + i]], 1);
}

__global__ void scan_kernel() {
    __shared__ int s[1024];
    const int t = threadIdx.x;
    const int CH = (NN + 1023) / 1024;
    int beg = t * CH;
    int end = beg + CH; if (end > NN) end = NN;
    int sum = 0;
    for (int i = beg; i < end; i++) sum += g_deg[i];
    int v = sum;
    s[t] = v;
    __syncthreads();
    for (int off = 1; off < 1024; off <<= 1) {
        int add = (t >= off) ? s[t - off] : 0;
        __syncthreads();
        v += add;
        s[t] = v;
        __syncthreads();
    }
    int run = (t == 0) ? 0 : s[t - 1];
    for (int i = beg; i < end; i++) { g_off[i] = run; run += g_deg[i]; }
    if (t == 1023) g_off[NN] = s[1023];
}

__global__ void cursor_kernel() {
    int i = blockIdx.x * blockDim.x + threadIdx.x;
    if (i < NN) g_cursor[i] = g_off[i];
}

__global__ void fill_kernel(const int* __restrict__ ei) {
    int i = blockIdx.x * blockDim.x + threadIdx.x;
    if (i < EE) {
        int s = ei[i];
        int d = ei[EE + i];
        int pos = atomicAdd(&g_cursor[d], 1);
        g_csr[pos] = s;
    } else if (i < ETOT) {
        int d = i - EE;
        int pos = atomicAdd(&g_cursor[d], 1);
        g_csr[pos] = d;
    }
}

// ---------------- tf32 tensor-core GEMM ----------------
// C[M,Ncols] = f(A) @ B^T (+bias) (+addmat[r%NN])  with optional BN(A) fusion
#define GBM 128
#define GBN 128
#define GBK 16
#define SKP 20

__device__ __forceinline__ uint32_t f2tf(float f) {
    uint32_t u;
    asm("cvt.rna.tf32.f32 %0, %1;" : "=r"(u) : "f"(f));
    return u;
}

__device__ __forceinline__ float4 fetch_one(const float* __restrict__ P, int ld,
                                            int K, int r, int gk, int R,
                                            const float* __restrict__ asc,
                                            const float* __restrict__ ash)
{
    float4 z = make_float4(0.f, 0.f, 0.f, 0.f);
    if (r >= R || gk >= K) return z;
    float4 v = *reinterpret_cast<const float4*>(P + (size_t)r * ld + gk);
    if (asc) {
        int t = r / NN;
        const float* sc = asc + (size_t)t * HCX + gk;
        const float* sh = ash + (size_t)t * HCX + gk;
        v.x = fmaxf(0.f, v.x * sc[0] + sh[0]);
        v.y = fmaxf(0.f, v.y * sc[1] + sh[1]);
        v.z = fmaxf(0.f, v.z * sc[2] + sh[2]);
        v.w = fmaxf(0.f, v.w * sc[3] + sh[3]);
    }
    return v;
}

__device__ __forceinline__ void mma_tf32(float c[4], uint32_t a0, uint32_t a1,
                                         uint32_t a2, uint32_t a3,
                                         uint32_t b0, uint32_t b1)
{
    asm volatile(
        "mma.sync.aligned.m16n8k8.row.col.f32.tf32.tf32.f32 "
        "{%0,%1,%2,%3}, {%4,%5,%6,%7}, {%8,%9}, {%0,%1,%2,%3};\n"
        : "+f"(c[0]), "+f"(c[1]), "+f"(c[2]), "+f"(c[3])
        : "r"(a0), "r"(a1), "r"(a2), "r"(a3), "r"(b0), "r"(b1));
}

__global__ __launch_bounds__(256)
void gemm_tc_kernel(int M, int Ncols, int K,
                    const float* __restrict__ A, int lda,
                    const float* __restrict__ B, int ldb,
                    const float* __restrict__ bias,
                    const float* __restrict__ asc,
                    const float* __restrict__ ash,
                    const float* __restrict__ addmat, int addld,
                    float* __restrict__ C, int ldc, int oproj)
{
    __shared__ uint32_t As[2][GBM][SKP];
    __shared__ uint32_t Bs[2][GBN][SKP];

    const int ktiles = (K + GBK - 1) / GBK;
    const int tid = threadIdx.x;
    const int brow = blockIdx.x * GBM;
    const int bcol = blockIdx.y * GBN;
    const int lane = tid & 31;
    const int warp = tid >> 5;
    const int g    = lane >> 2;
    const int tig  = lane & 3;
    const int wm   = warp & 1;
    const int wn   = warp >> 1;

    const int arow = tid >> 2;
    const int kq   = (tid & 3) * 4;

    float acc[4][4][4];
#pragma unroll
    for (int mt = 0; mt < 4; mt++)
#pragma unroll
        for (int nt = 0; nt < 4; nt++)
#pragma unroll
            for (int i = 0; i < 4; i++) acc[mt][nt][i] = 0.f;

    float4 rA0 = fetch_one(A, lda, K, brow + arow,      kq, M, asc, ash);
    float4 rA1 = fetch_one(A, lda, K, brow + arow + 64, kq, M, asc, ash);
    float4 rB0 = fetch_one(B, ldb, K, bcol + arow,      kq, Ncols, 0, 0);
    float4 rB1 = fetch_one(B, ldb, K, bcol + arow + 64, kq, Ncols, 0, 0);

    for (int kt = 0; kt < ktiles; kt++) {
        const int buf = kt & 1;
        As[buf][arow     ][kq+0] = f2tf(rA0.x); As[buf][arow     ][kq+1] = f2tf(rA0.y);
        As[buf][arow     ][kq+2] = f2tf(rA0.z); As[buf][arow     ][kq+3] = f2tf(rA0.w);
        As[buf][arow + 64][kq+0] = f2tf(rA1.x); As[buf][arow + 64][kq+1] = f2tf(rA1.y);
        As[buf][arow + 64][kq+2] = f2tf(rA1.z); As[buf][arow + 64][kq+3] = f2tf(rA1.w);
        Bs[buf][arow     ][kq+0] = f2tf(rB0.x); Bs[buf][arow     ][kq+1] = f2tf(rB0.y);
        Bs[buf][arow     ][kq+2] = f2tf(rB0.z); Bs[buf][arow     ][kq+3] = f2tf(rB0.w);
        Bs[buf][arow + 64][kq+0] = f2tf(rB1.x); Bs[buf][arow + 64][kq+1] = f2tf(rB1.y);
        Bs[buf][arow + 64][kq+2] = f2tf(rB1.z); Bs[buf][arow + 64][kq+3] = f2tf(rB1.w);
        __syncthreads();

        if (kt + 1 < ktiles) {
            int k0 = (kt + 1) * GBK;
            rA0 = fetch_one(A, lda, K, brow + arow,      k0 + kq, M, asc, ash);
            rA1 = fetch_one(A, lda, K, brow + arow + 64, k0 + kq, M, asc, ash);
            rB0 = fetch_one(B, ldb, K, bcol + arow,      k0 + kq, Ncols, 0, 0);
            rB1 = fetch_one(B, ldb, K, bcol + arow + 64, k0 + kq, Ncols, 0, 0);
        }

#pragma unroll
        for (int ks = 0; ks < 2; ks++) {
            const int kb = ks * 8;
            uint32_t af[4][4], bf[4][2];
#pragma unroll
            for (int mt = 0; mt < 4; mt++) {
                int r0 = wm * 64 + mt * 16 + g;
                af[mt][0] = As[buf][r0    ][kb + tig];
                af[mt][1] = As[buf][r0 + 8][kb + tig];
                af[mt][2] = As[buf][r0    ][kb + tig + 4];
                af[mt][3] = As[buf][r0 + 8][kb + tig + 4];
            }
#pragma unroll
            for (int nt = 0; nt < 4; nt++) {
                int cb = wn * 32 + nt * 8 + g;
                bf[nt][0] = Bs[buf][cb][kb + tig];
                bf[nt][1] = Bs[buf][cb][kb + tig + 4];
            }
#pragma unroll
            for (int mt = 0; mt < 4; mt++)
#pragma unroll
                for (int nt = 0; nt < 4; nt++)
                    mma_tf32(acc[mt][nt], af[mt][0], af[mt][1], af[mt][2], af[mt][3],
                             bf[nt][0], bf[nt][1]);
        }
        __syncthreads();
    }

#pragma unroll
    for (int mt = 0; mt < 4; mt++) {
        int gr0 = brow + wm * 64 + mt * 16 + g;
        int gr1 = gr0 + 8;
#pragma unroll
        for (int nt = 0; nt < 4; nt++) {
            int gc = bcol + wn * 32 + nt * 8 + 2 * tig;
            if (gc >= Ncols) continue;
            float bx = bias ? bias[gc]     : 0.f;
            float by = bias ? bias[gc + 1] : 0.f;
            if (gr0 < M) {
                float ax = bx, ay = by;
                if (addmat) {
                    const float* ad = addmat + (size_t)(gr0 % NN) * addld + gc;
                    ax += ad[0]; ay += ad[1];
                }
                float2 v = make_float2(acc[mt][nt][0] + ax, acc[mt][nt][1] + ay);
                size_t off = oproj ? ((size_t)(gr0 % NN) * (TT * EMBX) + (gr0 / NN) * EMBX + gc)
                                   : ((size_t)gr0 * ldc + gc);
                *reinterpret_cast<float2*>(C + off) = v;
            }
            if (gr1 < M) {
                float ax = bx, ay = by;
                if (addmat) {
                    const float* ad = addmat + (size_t)(gr1 % NN) * addld + gc;
                    ax += ad[0]; ay += ad[1];
                }
                float2 v = make_float2(acc[mt][nt][2] + ax, acc[mt][nt][3] + ay);
                size_t off = oproj ? ((size_t)(gr1 % NN) * (TT * EMBX) + (gr1 / NN) * EMBX + gc)
                                   : ((size_t)gr1 * ldc + gc);
                *reinterpret_cast<float2*>(C + off) = v;
            }
        }
    }
}

// ---------------- LSTM gate nonlinearity ----------------
__device__ __forceinline__ float sigm(float x) { return 1.f / (1.f + __expf(-x)); }

__global__ void lstm_gate_kernel(const float* __restrict__ G, int t, int hzero) {
    int i = blockIdx.x * blockDim.x + threadIdx.x;
    if (i >= NN * HLX) return;
    int n = i / HLX, j = i % HLX;
    const float* gx = g_gatesx + ((size_t)n * TT + t) * (4 * HLX);
    float vi = gx[j], vf = gx[HLX + j], vg = gx[2 * HLX + j], vo = gx[3 * HLX + j];
    if (!hzero) {
        const float* g = G + (size_t)n * (4 * HLX);
        vi += g[j]; vf += g[HLX + j]; vg += g[2 * HLX + j]; vo += g[3 * HLX + j];
    }
    float gi = sigm(vi);
    float gf = sigm(vf);
    float gg = tanhf(vg);
    float go = sigm(vo);
    float cold = hzero ? 0.f : g_c[i];
    float c = gf * cold + gi * gg;
    g_c[i] = c;
    g_hs[(size_t)t * NN * HLX + i] = go * tanhf(c);
}

// ---------------- GATv2 aggregation (batched over t, 2-way ILP) ----------------
__device__ __forceinline__ float4 leaky_add(float4 a, const float4& b) {
    float4 e;
    e.x = a.x + b.x; e.x = e.x > 0.f ? e.x : 0.2f * e.x;
    e.y = a.y + b.y; e.y = e.y > 0.f ? e.y : 0.2f * e.y;
    e.z = a.z + b.z; e.z = e.z > 0.f ? e.z : 0.2f * e.z;
    e.w = a.w + b.w; e.w = e.w > 0.f ? e.w : 0.2f * e.w;
    return e;
}

__global__ void gat_kernel(const float* __restrict__ xlxr,
                           const float* __restrict__ att,
                           const float* __restrict__ bias,
                           float* __restrict__ out)
{
    const int d = blockIdx.x;
    const int t = blockIdx.y;
    const int w = threadIdx.x >> 5;
    const int lane = threadIdx.x & 31;
    const int base = w * GCX + lane * 4;
    const size_t tbase = (size_t)t * NN;

    const float4 xrv = *reinterpret_cast<const float4*>(xlxr + (tbase + d) * XLD + HCX + base);
    const float4 av  = *reinterpret_cast<const float4*>(att + w * GCX + lane * 4);

    float mA = -1e30f, dA = 0.f, mB = -1e30f, dB = 0.f;
    float4 aA = make_float4(0.f, 0.f, 0.f, 0.f);
    float4 aB = make_float4(0.f, 0.f, 0.f, 0.f);

    const int beg = g_off[d], end = g_off[d + 1];
    int idx = beg;
    for (; idx + 1 < end; idx += 2) {
        int s0 = g_csr[idx];
        int s1 = g_csr[idx + 1];
        float4 x0 = *reinterpret_cast<const float4*>(xlxr + (tbase + s0) * XLD + base);
        float4 x1 = *reinterpret_cast<const float4*>(xlxr + (tbase + s1) * XLD + base);
        float4 e0 = leaky_add(x0, xrv);
        float4 e1 = leaky_add(x1, xrv);
        float p0 = e0.x * av.x + e0.y * av.y + e0.z * av.z + e0.w * av.w;
        float p1 = e1.x * av.x + e1.y * av.y + e1.z * av.z + e1.w * av.w;
#pragma unroll
        for (int off = 16; off; off >>= 1) {
            p0 += __shfl_xor_sync(0xffffffffu, p0, off);
            p1 += __shfl_xor_sync(0xffffffffu, p1, off);
        }
        // stream A
        {
            float nm = fmaxf(mA, p0);
            float sc = __expf(mA - nm);
            float e  = __expf(p0 - nm);
            aA.x = aA.x * sc + e * x0.x;
            aA.y = aA.y * sc + e * x0.y;
            aA.z = aA.z * sc + e * x0.z;
            aA.w = aA.w * sc + e * x0.w;
            dA = dA * sc + e;
            mA = nm;
        }
        // stream B
        {
            float nm = fmaxf(mB, p1);
            float sc = __expf(mB - nm);
            float e  = __expf(p1 - nm);
            aB.x = aB.x * sc + e * x1.x;
            aB.y = aB.y * sc + e * x1.y;
            aB.z = aB.z * sc + e * x1.z;
            aB.w = aB.w * sc + e * x1.w;
            dB = dB * sc + e;
            mB = nm;
        }
    }
    if (idx < end) {
        int s0 = g_csr[idx];
        float4 x0 = *reinterpret_cast<const float4*>(xlxr + (tbase + s0) * XLD + base);
        float4 e0 = leaky_add(x0, xrv);
        float p0 = e0.x * av.x + e0.y * av.y + e0.z * av.z + e0.w * av.w;
#pragma unroll
        for (int off = 16; off; off >>= 1) p0 += __shfl_xor_sync(0xffffffffu, p0, off);
        float nm = fmaxf(mA, p0);
        float sc = __expf(mA - nm);
        float e  = __expf(p0 - nm);
        aA.x = aA.x * sc + e * x0.x;
        aA.y = aA.y * sc + e * x0.y;
        aA.z = aA.z * sc + e * x0.z;
        aA.w = aA.w * sc + e * x0.w;
        dA = dA * sc + e;
        mA = nm;
    }

    // merge streams
    float m = fmaxf(mA, mB);
    float sA = __expf(mA - m);
    float sB = __expf(mB - m);
    float den = dA * sA + dB * sB;
    float4 acc;
    acc.x = aA.x * sA + aB.x * sB;
    acc.y = aA.y * sA + aB.y * sB;
    acc.z = aA.z * sA + aB.z * sB;
    acc.w = aA.w * sA + aB.w * sB;

    float inv = 1.f / den;
    float4 bv = *reinterpret_cast<const float4*>(bias + base);
    float4 o;
    o.x = acc.x * inv + bv.x;
    o.y = acc.y * inv + bv.y;
    o.z = acc.z * inv + bv.z;
    o.w = acc.w * inv + bv.w;
    *reinterpret_cast<float4*>(out + (tbase + d) * HCX + base) = o;
}

// ---------------- BatchNorm ----------------
__global__ void zero_stats_kernel() {
    int c = blockIdx.x * blockDim.x + threadIdx.x;
    if (c < TT * HCX) { g_sum[c] = 0.f; g_sumsq[c] = 0.f; }
}

#define BN_ROWS 200
__global__ void bn_stats_kernel(const float* __restrict__ x) {
    int c = threadIdx.x;
    int t = blockIdx.y;
    const float* xt = x + (size_t)t * NN * HCX;
    int rb = blockIdx.x * BN_ROWS;
    int re = rb + BN_ROWS; if (re > NN) re = NN;
    float s0 = 0.f, s1 = 0.f, q0 = 0.f, q1 = 0.f;
    for (int r = rb; r < re; r++) {
        float v0 = xt[(size_t)r * HCX + c];
        float v1 = xt[(size_t)r * HCX + c + 256];
        s0 += v0; q0 += v0 * v0;
        s1 += v1; q1 += v1 * v1;
    }
    atomicAdd(&g_sum[t * HCX + c], s0);
    atomicAdd(&g_sum[t * HCX + c + 256], s1);
    atomicAdd(&g_sumsq[t * HCX + c], q0);
    atomicAdd(&g_sumsq[t * HCX + c + 256], q1);
}

__global__ void bn_finalize_kernel(const float* __restrict__ gamma, const float* __restrict__ beta) {
    int c = threadIdx.x;
    int t = blockIdx.x;
    int i = t * HCX + c;
    float mean = g_sum[i] * (1.f / NN);
    float var  = g_sumsq[i] * (1.f / NN) - mean * mean;
    float a = gamma[c] * rsqrtf(var + 1e-5f);
    g_scale[i] = a;
    g_shift[i] = beta[c] - mean * a;
}

// ---------------- host side ----------------
static inline void launch_gemm(int M, int Ncols, int K,
                               const float* A, int lda, const float* B, int ldb,
                               const float* bias, const float* asc, const float* ash,
                               const float* addmat, int addld,
                               float* C, int ldc, int oproj)
{
    dim3 grid((M + GBM - 1) / GBM, (Ncols + GBN - 1) / GBN);
    gemm_tc_kernel<<<grid, 256>>>(M, Ncols, K, A, lda, B, ldb, bias, asc, ash,
                                  addmat, addld, C, ldc, oproj);
}

extern "C" void kernel_launch(void* const* d_in, const int* in_sizes, int n_in,
                              void* d_out, int out_size)
{
    const float* x_static = (const float*)d_in[0];
    const float* dyn      = (const float*)d_in[1];
    const int*   ei       = (const int*)  d_in[2];
    const float* W_ih     = (const float*)d_in[3];
    const float* W_hh     = (const float*)d_in[4];
    const float* b_ih     = (const float*)d_in[5];
    const float* b_hh     = (const float*)d_in[6];
    const float* Wl1      = (const float*)d_in[7];
    const float* Wr1      = (const float*)d_in[8];
    const float* att1     = (const float*)d_in[9];
    const float* bg1      = (const float*)d_in[10];
    const float* Wl2      = (const float*)d_in[11];
    const float* Wr2      = (const float*)d_in[12];
    const float* att2     = (const float*)d_in[13];
    const float* bg2      = (const float*)d_in[14];
    const float* gamma1   = (const float*)d_in[15];
    const float* beta1    = (const float*)d_in[16];
    const float* gamma2   = (const float*)d_in[17];
    const float* beta2    = (const float*)d_in[18];
    const float* Wp       = (const float*)d_in[19];
    const float* bp       = (const float*)d_in[20];
    float* out = (float*)d_out;

    void* p;
    cudaGetSymbolAddress(&p, g_hs);     float* hs    = (float*)p;
    cudaGetSymbolAddress(&p, g_AB);     float* AB    = (float*)p;
    cudaGetSymbolAddress(&p, g_bufC);   float* bC    = (float*)p;
    cudaGetSymbolAddress(&p, g_xscat);  float* xsc   = (float*)p;
    cudaGetSymbolAddress(&p, g_gate);   float* gate  = (float*)p;
    cudaGetSymbolAddress(&p, g_gatesx); float* gx    = (float*)p;
    cudaGetSymbolAddress(&p, g_WcatS);  float* WcS   = (float*)p;
    cudaGetSymbolAddress(&p, g_WcatD);  float* WcD   = (float*)p;
    cudaGetSymbolAddress(&p, g_Wcat2);  float* Wc2   = (float*)p;
    cudaGetSymbolAddress(&p, g_bsum);   float* bsum  = (float*)p;
    cudaGetSymbolAddress(&p, g_scale);  float* bscl  = (float*)p;
    cudaGetSymbolAddress(&p, g_shift);  float* bsh   = (float*)p;

    // --- setup: weight packing + fused bias + CSR build
    bsum_kernel<<<1, 512>>>(b_ih, b_hh);
    pack1_kernel<<<(XLD * IN1X + 255) / 256, 256>>>(Wl1, Wr1);
    pack2_kernel<<<(XLD * HCX + 255) / 256, 256>>>(Wl2, Wr2);
    init_deg_kernel<<<(NN + 255) / 256, 256>>>();
    count_kernel<<<(EE + 255) / 256, 256>>>(ei);
    scan_kernel<<<1, 1024>>>();
    cursor_kernel<<<(NN + 255) / 256, 256>>>();
    fill_kernel<<<(ETOT + 255) / 256, 256>>>(ei);

    // --- static projection (combined xl|xr, constant across t)
    launch_gemm(NN, XLD, DSX, x_static, DSX, WcS, DSX,
                0, 0, 0, 0, 0, xsc, XLD, 0);

    // --- LSTM input-side gates for all (n,t) in one GEMM
    launch_gemm(TNN, 4 * HLX, DDIM, dyn, DDIM, W_ih, DDIM,
                bsum, 0, 0, 0, 0, gx, 4 * HLX, 0);

    // --- LSTM recurrence
    lstm_gate_kernel<<<(NN * HLX + 255) / 256, 256>>>(gate, 0, 1);
    for (int t = 1; t < TT; t++) {
        launch_gemm(NN, 4 * HLX, HLX, hs + (size_t)(t - 1) * NN * HLX, HLX, W_hh, HLX,
                    0, 0, 0, 0, 0, gate, 4 * HLX, 0);
        lstm_gate_kernel<<<(NN * HLX + 255) / 256, 256>>>(gate, t, 0);
    }

    // --- layer 1 (batched, combined xl|xr): AB = hs @ WcD^T + xsc[r%NN]
    launch_gemm(TNN, XLD, HLX, hs, HLX, WcD, HLX,
                0, 0, 0, xsc, XLD, AB, XLD, 0);
    gat_kernel<<<dim3(NN, TT), 128>>>(AB, att1, bg1, bC);

    zero_stats_kernel<<<TT, 512>>>();
    bn_stats_kernel<<<dim3((NN + BN_ROWS - 1) / BN_ROWS, TT), 256>>>(bC);
    bn_finalize_kernel<<<TT, 512>>>(gamma1, beta1);

    // --- layer 2 (batched, combined, BN1+relu fused into A fetch)
    launch_gemm(TNN, XLD, HCX, bC, HCX, Wc2, HCX,
                0, bscl, bsh, 0, 0, AB, XLD, 0);
    gat_kernel<<<dim3(NN, TT), 128>>>(AB, att2, bg2, bC);

    zero_stats_kernel<<<TT, 512>>>();
    bn_stats_kernel<<<dim3((NN + BN_ROWS - 1) / BN_ROWS, TT), 256>>>(bC);
    bn_finalize_kernel<<<TT, 512>>>(gamma2, beta2);

    // --- projection (batched, BN2+relu fused, output remapped to [N,T,EMB])
    launch_gemm(TNN, EMBX, HCX, bC, HCX, Wp, HCX,
                bp, bscl, bsh, 0, 0, out, 0, 1);
}